// round 9
// baseline (speedup 1.0000x reference)
#include <cuda_runtime.h>
#include <cuda_bf16.h>
#include <math.h>
#include <stdint.h>

// Problem constants
#define BB 8
#define CC 128
#define HH 96
#define WW 96
#define PP (HH*WW)       // 9216
#define NG 16            // groups
#define CPG 8            // channels per group
#define NBLK 288         // stats/df blocks (BB*PP/256)
#define BPB 36           // blocks per batch (PP/256)

// ---------------- scratch (device globals; no allocs allowed) ----------------
__device__ float g_avg [BB*PP];
__device__ float g_invn[BB*PP];
__device__ float g_df  [BB*PP];
__device__ float g_ps  [NBLK*NG];
__device__ float g_pss [NBLK*NG];
__device__ float g_pmn [NBLK];
__device__ float g_pmx [NBLK];
__device__ float g_gnm [BB*NG];
__device__ float g_gni [BB*NG];
__device__ float g_mnv [BB];
__device__ float g_mxv [BB];
__device__ float g_enh [BB*CC*PP];         // enhanced (out + groupnorm)
__device__ uint4 g_w1f [16*8*32];          // w1 bf16x2 in mma-fragment order
__device__ uint4 g_w2f [8*16*32];          // w2 bf16x2 in mma-fragment order

__device__ __forceinline__ unsigned packbf(float lo, float hi) {
    unsigned d;
    asm("cvt.rn.bf16x2.f32 %0, %1, %2;" : "=r"(d) : "f"(hi), "f"(lo));
    return d;
}

// ---------------- K1: per-pixel avg & inv-norm, per-(b,g) partial sums -------
// blocks >= NBLK convert w1/w2 to bf16x2 fragment layout instead.
__global__ void k_stats(const float* __restrict__ x,
                        const float* __restrict__ w1,
                        const float* __restrict__ w2) {
    int tid = threadIdx.x;
    if (blockIdx.x >= NBLK) {
        int idx = (blockIdx.x - NBLK) * 256 + tid;     // 0..8191
        int lane = idx & 31, lk = lane & 3, lm = lane >> 2;
        int kw;
        if (idx < 4096) {                              // w1: 16 m-groups x 8 steps
            int m16 = idx >> 8, st = (idx >> 5) & 7;
            int mr = m16*16 + lm; kw = st*8;
            uint4 v;
            v.x = packbf(w1[mr*128     + 2*(kw+lk)],   w1[mr*128     + 2*(kw+lk)+1]);
            v.y = packbf(w1[(mr+8)*128 + 2*(kw+lk)],   w1[(mr+8)*128 + 2*(kw+lk)+1]);
            v.z = packbf(w1[mr*128     + 2*(kw+4+lk)], w1[mr*128     + 2*(kw+4+lk)+1]);
            v.w = packbf(w1[(mr+8)*128 + 2*(kw+4+lk)], w1[(mr+8)*128 + 2*(kw+4+lk)+1]);
            g_w1f[idx] = v;
        } else {                                       // w2: 8 m-groups x 16 steps
            int j = idx - 4096;
            int m16 = j >> 9, st = (j >> 5) & 15;
            int mr = m16*16 + lm; kw = st*8;
            uint4 v;
            v.x = packbf(w2[mr*256     + 2*(kw+lk)],   w2[mr*256     + 2*(kw+lk)+1]);
            v.y = packbf(w2[(mr+8)*256 + 2*(kw+lk)],   w2[(mr+8)*256 + 2*(kw+lk)+1]);
            v.z = packbf(w2[mr*256     + 2*(kw+4+lk)], w2[mr*256     + 2*(kw+4+lk)+1]);
            v.w = packbf(w2[(mr+8)*256 + 2*(kw+4+lk)], w2[(mr+8)*256 + 2*(kw+4+lk)+1]);
            g_w2f[j] = v;
        }
        return;
    }

    int idx = blockIdx.x * 256 + tid;        // (b,p)
    int b = idx / PP;
    const float* xb = x + (size_t)b * CC * PP + (idx - b*PP);
    int lane = tid & 31;

    __shared__ float s_gs[NG], s_gss[NG];
    if (tid < NG) { s_gs[tid] = 0.f; s_gss[tid] = 0.f; }
    __syncthreads();

    float sum = 0.f, ssq = 0.f;
    #pragma unroll
    for (int g = 0; g < NG; g++) {
        float gs = 0.f, gss = 0.f;
        #pragma unroll
        for (int cc = 0; cc < CPG; cc++) {
            float v = xb[(size_t)(g*CPG + cc) * PP];
            gs += v; gss += v*v;
        }
        sum += gs; ssq += gss;
        #pragma unroll
        for (int off = 16; off; off >>= 1) {
            gs  += __shfl_xor_sync(0xffffffffu, gs,  off);
            gss += __shfl_xor_sync(0xffffffffu, gss, off);
        }
        if (lane == 0) { atomicAdd(&s_gs[g], gs); atomicAdd(&s_gss[g], gss); }
    }
    __syncthreads();
    if (tid < NG) {
        g_ps [blockIdx.x*NG + tid] = s_gs [tid];
        g_pss[blockIdx.x*NG + tid] = s_gss[tid];
    }
    g_avg [idx] = sum * (1.f/128.f);
    g_invn[idx] = 1.f / fmaxf(sqrtf(ssq), 1e-12f);
}

// ---------------- K2: laplacian of avg (zero pad), per-block min/max ---------
__global__ void k_df() {
    int tid = threadIdx.x;
    int idx = blockIdx.x * 256 + tid;
    int b = idx / PP;
    int p = idx - b*PP;
    int y = p / WW, xq = p - y*WW;
    float c = g_avg[idx];
    float up = (y > 0)      ? g_avg[idx - WW] : 0.f;
    float dn = (y < HH-1)   ? g_avg[idx + WW] : 0.f;
    float lf = (xq > 0)     ? g_avg[idx - 1]  : 0.f;
    float rt = (xq < WW-1)  ? g_avg[idx + 1]  : 0.f;
    float df = fabsf(4.f*c - up - dn - lf - rt);
    g_df[idx] = df;

    __shared__ float smn[256], smx[256];
    smn[tid] = df; smx[tid] = df;
    __syncthreads();
    for (int s = 128; s; s >>= 1) {
        if (tid < s) {
            smn[tid] = fminf(smn[tid], smn[tid+s]);
            smx[tid] = fmaxf(smx[tid], smx[tid+s]);
        }
        __syncthreads();
    }
    if (tid == 0) { g_pmn[blockIdx.x] = smn[0]; g_pmx[blockIdx.x] = smx[0]; }
}

// ---------------- K3: reduce partials -> GN stats + per-batch min/max --------
__global__ void k_gn() {
    int i = threadIdx.x;          // (b,g)
    int b = i >> 4, g = i & 15;
    float s = 0.f, ss = 0.f;
    for (int l = 0; l < BPB; l++) {
        s  += g_ps [(b*BPB + l)*NG + g];
        ss += g_pss[(b*BPB + l)*NG + g];
    }
    const float N = (float)(CPG * PP);
    float mean = s / N;
    float var = ss / N - mean*mean;
    g_gnm[i] = mean;
    g_gni[i] = rsqrtf(var + 1e-5f);

    if (i < BB) {
        float mn = g_pmn[i*BPB], mx = g_pmx[i*BPB];
        for (int l = 1; l < BPB; l++) {
            mn = fminf(mn, g_pmn[i*BPB + l]);
            mx = fmaxf(mx, g_pmx[i*BPB + l]);
        }
        g_mnv[i] = mn; g_mxv[i] = mx;
    }
}

// ---------------- K4: IPG core, register-resident pixel pairs (no big smem) --
// Thread owns pixel pair (gx, gx+1). Per channel per row: 3 aligned float2
// loads (P/C/N) give positions gx-1..gx+2. Reflect: left edge -> C.y,
// right edge -> C.x (no OOB loads needed).

#define CE(a_,b_) do { \
    if ((sv[b_] > sv[a_]) || (sv[b_] == sv[a_] && si[b_] < si[a_])) { \
        float t_ = sv[a_]; sv[a_] = sv[b_]; sv[b_] = t_; \
        int u_ = si[a_]; si[a_] = si[b_]; si[b_] = u_; } \
} while (0)

__device__ __forceinline__ void topk9(const float sims[9], int k, float wj[9]) {
    float sv[9]; int si[9];
    #pragma unroll
    for (int j = 0; j < 9; j++) { sv[j] = sims[j]; si[j] = j; }
    CE(0,3); CE(1,7); CE(2,5); CE(4,8);
    CE(0,7); CE(2,4); CE(3,8); CE(5,6);
    CE(0,2); CE(1,3); CE(4,5); CE(7,8);
    CE(1,4); CE(3,6); CE(5,7);
    CE(0,1); CE(2,4); CE(3,5); CE(6,8);
    CE(2,3); CE(4,5); CE(6,7);
    CE(1,2); CE(3,4); CE(5,6);
    float ts = sv[0]; int tix = si[0];
    #pragma unroll
    for (int r = 0; r < 9; r++) { if (r == k-1) { ts = sv[r]; tix = si[r]; } }
    float ws = 0.f;
    #pragma unroll
    for (int j = 0; j < 9; j++) {
        bool sel = (sims[j] > ts) || (sims[j] == ts && j <= tix);
        wj[j] = sel ? expf(sims[j]) : 0.f;
        ws += wj[j];
    }
    float iws = 1.f / ws;
    #pragma unroll
    for (int j = 0; j < 9; j++) wj[j] *= iws;
}

// load one row's 4 needed values (gx-1 .. gx+2) from base pointer p (row base
// pre-added, at column gx). lb/rb are image-edge predicates.
#define LOADROW(p_, off_, V) do { \
    float2 Cv = *(const float2*)((p_) + (off_)); \
    float2 Pv = lb ? Cv : *(const float2*)((p_) + (off_) - 2); \
    float2 Nv = rb ? Cv : *(const float2*)((p_) + (off_) + 2); \
    V[0] = lb ? Cv.y : Pv.y; V[1] = Cv.x; V[2] = Cv.y; V[3] = rb ? Cv.x : Nv.x; \
} while (0)

__global__ void __launch_bounds__(128) k_main(const float* __restrict__ x,
                                              const float* __restrict__ gnw,
                                              const float* __restrict__ gnb) {
    __shared__ float s_gnw[CC], s_gnb[CC], s_gnm[NG], s_gni[NG];
    int b = blockIdx.z;
    int tid = threadIdx.y * 16 + threadIdx.x;
    if (tid < NG) { s_gnm[tid] = g_gnm[b*NG+tid]; s_gni[tid] = g_gni[b*NG+tid]; }
    s_gnw[tid] = gnw[tid]; s_gnb[tid] = gnb[tid];
    __syncthreads();

    int T  = blockIdx.x * 16 + threadIdx.x;     // pair index 0..47
    int y  = blockIdx.y * 8  + threadIdx.y;     // row 0..95
    int gx = 2 * T;
    bool lb = (gx == 0), rb = (gx == WW - 2);
    int yu = (y > 0) ? y - 1 : 1;
    int yd = (y < HH-1) ? y + 1 : HH - 2;
    int r0 = yu*WW + gx, r1 = y*WW + gx, r2 = yd*WW + gx;

    const float* xb = x + (size_t)b * CC * PP;

    float d0[9], d1[9];
    #pragma unroll
    for (int j = 0; j < 9; j++) { d0[j] = 0.f; d1[j] = 0.f; }

    // pass 1: dot products over all channels
    #pragma unroll 2
    for (int c = 0; c < CC; c++) {
        const float* p = xb + (size_t)c * PP;
        float va[4], vb[4], vc[4];
        LOADROW(p, r0, va);
        LOADROW(p, r1, vb);
        LOADROW(p, r2, vc);
        float c0 = vb[1], c1 = vb[2];
        d0[0] += c0*va[0]; d0[1] += c0*va[1]; d0[2] += c0*va[2];
        d0[3] += c0*vb[0]; d0[4] += c0*vb[1]; d0[5] += c0*vb[2];
        d0[6] += c0*vc[0]; d0[7] += c0*vc[1]; d0[8] += c0*vc[2];
        d1[0] += c1*va[1]; d1[1] += c1*va[2]; d1[2] += c1*va[3];
        d1[3] += c1*vb[1]; d1[4] += c1*vb[2]; d1[5] += c1*vb[3];
        d1[6] += c1*vc[1]; d1[7] += c1*vc[2]; d1[8] += c1*vc[3];
    }

    // inverse norms for the 12 neighbor positions
    const float* ivp = g_invn + (size_t)b * PP;
    float i0[4], i1[4], i2[4];
    LOADROW(ivp, r0, i0);
    LOADROW(ivp, r1, i1);
    LOADROW(ivp, r2, i2);
    float ic0 = i1[1], ic1 = i1[2];

    float s0[9], s1[9];
    #pragma unroll
    for (int dc = 0; dc < 3; dc++) {
        s0[dc]   = d0[dc]   * ic0 * i0[dc];
        s0[3+dc] = d0[3+dc] * ic0 * i1[dc];
        s0[6+dc] = d0[6+dc] * ic0 * i2[dc];
        s1[dc]   = d1[dc]   * ic1 * i0[dc+1];
        s1[3+dc] = d1[3+dc] * ic1 * i1[dc+1];
        s1[6+dc] = d1[6+dc] * ic1 * i2[dc+1];
    }

    // connection counts
    float2 dfv = *(const float2*)&g_df[(size_t)b*PP + r1];
    float mn = g_mnv[b], mx = g_mxv[b];
    float inv_rng = 1.f / (mx - mn + 1e-8f);
    int k0 = 1 + (int)rintf((dfv.x - mn) * inv_rng * 7.f);
    int k1 = 1 + (int)rintf((dfv.y - mn) * inv_rng * 7.f);
    if (k0 < 1) k0 = 1; if (k0 > 8) k0 = 8;
    if (k1 < 1) k1 = 1; if (k1 > 8) k1 = 8;

    float w0[9], w1v[9];
    topk9(s0, k0, w0);
    topk9(s1, k1, w1v);

    // pass 2: weighted neighbor sum + groupnorm -> enhanced
    #pragma unroll 2
    for (int c = 0; c < CC; c++) {
        const float* p = xb + (size_t)c * PP;
        float va[4], vb[4], vc[4];
        LOADROW(p, r0, va);
        LOADROW(p, r1, vb);
        LOADROW(p, r2, vc);
        float a0 = w0[0]*va[0] + w0[1]*va[1] + w0[2]*va[2]
                 + w0[3]*vb[0] + w0[4]*vb[1] + w0[5]*vb[2]
                 + w0[6]*vc[0] + w0[7]*vc[1] + w0[8]*vc[2];
        float a1 = w1v[0]*va[1] + w1v[1]*va[2] + w1v[2]*va[3]
                 + w1v[3]*vb[1] + w1v[4]*vb[2] + w1v[5]*vb[3]
                 + w1v[6]*vc[1] + w1v[7]*vc[2] + w1v[8]*vc[3];
        int g = c >> 3;
        float gm = s_gnm[g], gi = s_gni[g];
        float2 o;
        o.x = a0 + (vb[1] - gm)*gi*s_gnw[c] + s_gnb[c];
        o.y = a1 + (vb[2] - gm)*gi*s_gnw[c] + s_gnb[c];
        *(float2*)&g_enh[(size_t)(b*CC + c) * PP + r1] = o;
    }
}

// ---------------- K5: fused FFN (bf16 mma, fragment-order W, H in smem) ------
#define NT 128
#define ESTR 68      // words per n-row of Es (K=128 -> 64 words + 4 pad)
#define HSTR 132     // words per n-row of Hs (K=256 -> 128 words + 4 pad)

#define MMA_BF16(C, A, B2) asm volatile( \
    "mma.sync.aligned.m16n8k16.row.col.f32.bf16.bf16.f32 " \
    "{%0,%1,%2,%3}, {%4,%5,%6,%7}, {%8,%9}, {%0,%1,%2,%3};\n" \
    : "+f"((C)[0]), "+f"((C)[1]), "+f"((C)[2]), "+f"((C)[3]) \
    : "r"((A)[0]), "r"((A)[1]), "r"((A)[2]), "r"((A)[3]), \
      "r"((B2)[0]), "r"((B2)[1]))

__global__ void __launch_bounds__(512, 1) k_ffn(const float* __restrict__ b1,
                                                const float* __restrict__ b2,
                                                float* __restrict__ out) {
    extern __shared__ unsigned smu[];
    unsigned* Es = smu;                     // [128][ESTR]
    unsigned* Hs = Es + 128*ESTR;           // [128][HSTR]

    int b = blockIdx.y;
    int n0 = blockIdx.x * NT;
    int tid = threadIdx.x;
    int warp = tid >> 5, lane = tid & 31;
    int lm = lane >> 2, lk = lane & 3;

    const float* E = g_enh + (size_t)b * CC * PP + n0;

    // ---- Es fill: E[k][n] fp32 -> bf16x2 pairs along k, n-major layout ----
    #pragma unroll
    for (int j = 0; j < 16; j++) {
        int i = tid + 512*j;
        int w = i >> 7, n = i & 127;
        float lo = E[(size_t)(2*w)   * PP + n];
        float hi = E[(size_t)(2*w+1) * PP + n];
        Es[n*ESTR + w] = packbf(lo, hi);
    }
    __syncthreads();

    // ---- GEMM1: warp tile 32(M) x 64(N); 8 warp-rows x 2 warp-cols ----
    int wm1 = (warp >> 1) * 32, wn1 = (warp & 1) * 64;
    int m16a = wm1 >> 4;
    float c1[2][8][4];
    #pragma unroll
    for (int mt = 0; mt < 2; mt++)
        #pragma unroll
        for (int nt = 0; nt < 8; nt++)
            #pragma unroll
            for (int q = 0; q < 4; q++) c1[mt][nt][q] = 0.f;

    #pragma unroll
    for (int st = 0; st < 8; st++) {           // 8 k16 steps
        int kw = st * 8;
        unsigned a[2][4], bw[8][2];
        *(uint4*)a[0] = g_w1f[((m16a    )*8 + st)*32 + lane];
        *(uint4*)a[1] = g_w1f[((m16a + 1)*8 + st)*32 + lane];
        #pragma unroll
        for (int nt = 0; nt < 8; nt++) {
            int nc = wn1 + nt*8 + lm;
            bw[nt][0] = Es[nc*ESTR + kw + lk];
            bw[nt][1] = Es[nc*ESTR + kw + 4 + lk];
        }
        #pragma unroll
        for (int mt = 0; mt < 2; mt++)
            #pragma unroll
            for (int nt = 0; nt < 8; nt++)
                MMA_BF16(c1[mt][nt], a[mt], bw[nt]);
    }

    // ---- H: bias + relu, pack row pairs via shfl, store n-major bf16 ----
    #pragma unroll
    for (int mt = 0; mt < 2; mt++) {
        int mr = wm1 + mt*16 + lm;
        float bi0 = b1[mr], bi1 = b1[mr + 8];
        #pragma unroll
        for (int nt = 0; nt < 8; nt++) {
            float v0 = fmaxf(c1[mt][nt][0] + bi0, 0.f);
            float v1 = fmaxf(c1[mt][nt][1] + bi0, 0.f);
            float v2 = fmaxf(c1[mt][nt][2] + bi1, 0.f);
            float v3 = fmaxf(c1[mt][nt][3] + bi1, 0.f);
            float p0 = __shfl_xor_sync(0xffffffffu, v0, 4);
            float p1 = __shfl_xor_sync(0xffffffffu, v1, 4);
            float p2 = __shfl_xor_sync(0xffffffffu, v2, 4);
            float p3 = __shfl_xor_sync(0xffffffffu, v3, 4);
            if (!(lm & 1)) {                      // even rows pack (mr, mr+1)
                int colA = wn1 + nt*8 + 2*lk;
                int w0 = mr >> 1;
                Hs[colA    *HSTR + w0]     = packbf(v0, p0);
                Hs[(colA+1)*HSTR + w0]     = packbf(v1, p1);
                Hs[colA    *HSTR + w0 + 4] = packbf(v2, p2);
                Hs[(colA+1)*HSTR + w0 + 4] = packbf(v3, p3);
            }
        }
    }
    __syncthreads();

    // ---- GEMM2: warp tile 32(M) x 32(N); 4 warp-rows x 4 warp-cols ----
    int wm2 = (warp >> 2) * 32, wn2 = (warp & 3) * 32;
    int m16b = wm2 >> 4;
    float c2[2][4][4];
    #pragma unroll
    for (int mt = 0; mt < 2; mt++)
        #pragma unroll
        for (int nt = 0; nt < 4; nt++)
            #pragma unroll
            for (int q = 0; q < 4; q++) c2[mt][nt][q] = 0.f;

    #pragma unroll
    for (int st = 0; st < 16; st++) {          // 16 k16 steps
        int kw = st * 8;
        unsigned a[2][4], bw[4][2];
        *(uint4*)a[0] = g_w2f[((m16b    )*16 + st)*32 + lane];
        *(uint4*)a[1] = g_w2f[((m16b + 1)*16 + st)*32 + lane];
        #pragma unroll
        for (int nt = 0; nt < 4; nt++) {
            int nc = wn2 + nt*8 + lm;
            bw[nt][0] = Hs[nc*HSTR + kw + lk];
            bw[nt][1] = Hs[nc*HSTR + kw + 4 + lk];
        }
        #pragma unroll
        for (int mt = 0; mt < 2; mt++)
            #pragma unroll
            for (int nt = 0; nt < 4; nt++)
                MMA_BF16(c2[mt][nt], a[mt], bw[nt]);
    }

    // ---- epilogue: out = enhanced + ffn + b2 ----
    #pragma unroll
    for (int mt = 0; mt < 2; mt++) {
        int mr = wm2 + mt*16 + lm;
        float bi0 = b2[mr], bi1 = b2[mr + 8];
        #pragma unroll
        for (int nt = 0; nt < 4; nt++) {
            int col = wn2 + nt*8 + 2*lk;
            size_t o0 = (size_t)(b*CC + mr) * PP + n0 + col;
            size_t o1 = o0 + (size_t)8 * PP;
            float2 e0 = *(const float2*)&g_enh[o0];
            float2 e1 = *(const float2*)&g_enh[o1];
            float2 v0, v1;
            v0.x = c2[mt][nt][0] + bi0 + e0.x;
            v0.y = c2[mt][nt][1] + bi0 + e0.y;
            v1.x = c2[mt][nt][2] + bi1 + e1.x;
            v1.y = c2[mt][nt][3] + bi1 + e1.y;
            *(float2*)&out[o0] = v0;
            *(float2*)&out[o1] = v1;
        }
    }
}

// ---------------- launch ----------------
extern "C" void kernel_launch(void* const* d_in, const int* in_sizes, int n_in,
                              void* d_out, int out_size) {
    const float* x   = (const float*)d_in[0];
    const float* gnw = (const float*)d_in[1];
    const float* gnb = (const float*)d_in[2];
    const float* w1  = (const float*)d_in[3];
    const float* b1  = (const float*)d_in[4];
    const float* w2  = (const float*)d_in[5];
    const float* b2  = (const float*)d_in[6];
    float* out = (float*)d_out;

    const int smem_ffn = (128*ESTR + 128*HSTR) * 4;        // 102400 B
    cudaFuncSetAttribute(k_ffn, cudaFuncAttributeMaxDynamicSharedMemorySize, smem_ffn);

    k_stats<<<NBLK + 32, 256>>>(x, w1, w2);                // +32 blocks: W->frag bf16
    k_df   <<<NBLK, 256>>>();
    k_gn   <<<1, 128>>>();
    k_main <<<dim3(3, 12, BB), dim3(16, 8)>>>(x, gnw, gnb);
    k_ffn  <<<dim3(PP/NT, BB), 512, smem_ffn>>>(b1, b2, out);
}

// round 10
// speedup vs baseline: 2.2485x; 2.2485x over previous
#include <cuda_runtime.h>
#include <cuda_bf16.h>
#include <math.h>
#include <stdint.h>

// Problem constants
#define BB 8
#define CC 128
#define HH 96
#define WW 96
#define PP (HH*WW)       // 9216
#define NG 16            // groups
#define CPG 8            // channels per group
#define NBLK 288         // stats/df blocks (BB*PP/256)
#define BPB 36           // blocks per batch (PP/256)

// ---------------- scratch (device globals; no allocs allowed) ----------------
__device__ float g_avg [BB*PP];
__device__ float g_invn[BB*PP];
__device__ float g_df  [BB*PP];
__device__ float g_ps  [NBLK*NG];
__device__ float g_pss [NBLK*NG];
__device__ float g_pmn [NBLK];
__device__ float g_pmx [NBLK];
__device__ float g_gnm [BB*NG];
__device__ float g_gni [BB*NG];
__device__ float g_mnv [BB];
__device__ float g_mxv [BB];
__device__ float g_enh [BB*CC*PP];         // enhanced (out + groupnorm)
__device__ uint4 g_w1f [16*8*32];          // w1 bf16x2 in mma-fragment order
__device__ uint4 g_w2f [8*16*32];          // w2 bf16x2 in mma-fragment order

__device__ __forceinline__ int refl(int i) {
    return i < 0 ? -i : (i >= HH ? 2*HH - 2 - i : i);
}

__device__ __forceinline__ unsigned packbf(float lo, float hi) {
    unsigned d;
    asm("cvt.rn.bf16x2.f32 %0, %1, %2;" : "=r"(d) : "f"(hi), "f"(lo));
    return d;
}

// ---------------- K1: per-pixel avg & inv-norm, per-(b,g) partial sums -------
// blocks >= NBLK convert w1/w2 to bf16x2 fragment layout instead.
__global__ void k_stats(const float* __restrict__ x,
                        const float* __restrict__ w1,
                        const float* __restrict__ w2) {
    int tid = threadIdx.x;
    if (blockIdx.x >= NBLK) {
        int idx = (blockIdx.x - NBLK) * 256 + tid;     // 0..8191
        int lane = idx & 31, lk = lane & 3, lm = lane >> 2;
        int kw;
        if (idx < 4096) {                              // w1: 16 m-groups x 8 steps
            int m16 = idx >> 8, st = (idx >> 5) & 7;
            int mr = m16*16 + lm; kw = st*8;
            uint4 v;
            v.x = packbf(w1[mr*128     + 2*(kw+lk)],   w1[mr*128     + 2*(kw+lk)+1]);
            v.y = packbf(w1[(mr+8)*128 + 2*(kw+lk)],   w1[(mr+8)*128 + 2*(kw+lk)+1]);
            v.z = packbf(w1[mr*128     + 2*(kw+4+lk)], w1[mr*128     + 2*(kw+4+lk)+1]);
            v.w = packbf(w1[(mr+8)*128 + 2*(kw+4+lk)], w1[(mr+8)*128 + 2*(kw+4+lk)+1]);
            g_w1f[idx] = v;
        } else {                                       // w2: 8 m-groups x 16 steps
            int j = idx - 4096;
            int m16 = j >> 9, st = (j >> 5) & 15;
            int mr = m16*16 + lm; kw = st*8;
            uint4 v;
            v.x = packbf(w2[mr*256     + 2*(kw+lk)],   w2[mr*256     + 2*(kw+lk)+1]);
            v.y = packbf(w2[(mr+8)*256 + 2*(kw+lk)],   w2[(mr+8)*256 + 2*(kw+lk)+1]);
            v.z = packbf(w2[mr*256     + 2*(kw+4+lk)], w2[mr*256     + 2*(kw+4+lk)+1]);
            v.w = packbf(w2[(mr+8)*256 + 2*(kw+4+lk)], w2[(mr+8)*256 + 2*(kw+4+lk)+1]);
            g_w2f[j] = v;
        }
        return;
    }

    int idx = blockIdx.x * 256 + tid;        // (b,p)
    int b = idx / PP;
    const float* xb = x + (size_t)b * CC * PP + (idx - b*PP);
    int lane = tid & 31;

    __shared__ float s_gs[NG], s_gss[NG];
    if (tid < NG) { s_gs[tid] = 0.f; s_gss[tid] = 0.f; }
    __syncthreads();

    float sum = 0.f, ssq = 0.f;
    #pragma unroll
    for (int g = 0; g < NG; g++) {
        float gs = 0.f, gss = 0.f;
        #pragma unroll
        for (int cc = 0; cc < CPG; cc++) {
            float v = xb[(size_t)(g*CPG + cc) * PP];
            gs += v; gss += v*v;
        }
        sum += gs; ssq += gss;
        #pragma unroll
        for (int off = 16; off; off >>= 1) {
            gs  += __shfl_xor_sync(0xffffffffu, gs,  off);
            gss += __shfl_xor_sync(0xffffffffu, gss, off);
        }
        if (lane == 0) { atomicAdd(&s_gs[g], gs); atomicAdd(&s_gss[g], gss); }
    }
    __syncthreads();
    if (tid < NG) {
        g_ps [blockIdx.x*NG + tid] = s_gs [tid];
        g_pss[blockIdx.x*NG + tid] = s_gss[tid];
    }
    g_avg [idx] = sum * (1.f/128.f);
    g_invn[idx] = 1.f / fmaxf(sqrtf(ssq), 1e-12f);
}

// ---------------- K2: laplacian of avg (zero pad), per-block min/max ---------
__global__ void k_df() {
    int tid = threadIdx.x;
    int idx = blockIdx.x * 256 + tid;
    int b = idx / PP;
    int p = idx - b*PP;
    int y = p / WW, xq = p - y*WW;
    float c = g_avg[idx];
    float up = (y > 0)      ? g_avg[idx - WW] : 0.f;
    float dn = (y < HH-1)   ? g_avg[idx + WW] : 0.f;
    float lf = (xq > 0)     ? g_avg[idx - 1]  : 0.f;
    float rt = (xq < WW-1)  ? g_avg[idx + 1]  : 0.f;
    float df = fabsf(4.f*c - up - dn - lf - rt);
    g_df[idx] = df;

    __shared__ float smn[256], smx[256];
    smn[tid] = df; smx[tid] = df;
    __syncthreads();
    for (int s = 128; s; s >>= 1) {
        if (tid < s) {
            smn[tid] = fminf(smn[tid], smn[tid+s]);
            smx[tid] = fmaxf(smx[tid], smx[tid+s]);
        }
        __syncthreads();
    }
    if (tid == 0) { g_pmn[blockIdx.x] = smn[0]; g_pmx[blockIdx.x] = smx[0]; }
}

// ---------------- K3: reduce partials -> GN stats + per-batch min/max --------
__global__ void k_gn() {
    int i = threadIdx.x;          // (b,g)
    int b = i >> 4, g = i & 15;
    float s = 0.f, ss = 0.f;
    for (int l = 0; l < BPB; l++) {
        s  += g_ps [(b*BPB + l)*NG + g];
        ss += g_pss[(b*BPB + l)*NG + g];
    }
    const float N = (float)(CPG * PP);
    float mean = s / N;
    float var = ss / N - mean*mean;
    g_gnm[i] = mean;
    g_gni[i] = rsqrtf(var + 1e-5f);

    if (i < BB) {
        float mn = g_pmn[i*BPB], mx = g_pmx[i*BPB];
        for (int l = 1; l < BPB; l++) {
            mn = fminf(mn, g_pmn[i*BPB + l]);
            mx = fmaxf(mx, g_pmx[i*BPB + l]);
        }
        g_mnv[i] = mn; g_mxv[i] = mx;
    }
}

// ---------------- K4: IPG core (R3 variant: single fill, all channels) -------
#define TW 32
#define TH 8
#define ROWW 34          // TW+2
#define TILE (10*ROWW)   // 340
#define CSTR 132         // channel stride (128+4)

#define CE(a_,b_) do { \
    if ((sv[b_] > sv[a_]) || (sv[b_] == sv[a_] && si[b_] < si[a_])) { \
        float t_ = sv[a_]; sv[a_] = sv[b_]; sv[b_] = t_; \
        int u_ = si[a_]; si[a_] = si[b_]; si[b_] = u_; } \
} while (0)

__global__ void __launch_bounds__(256) k_main(const float* __restrict__ x,
                                              const float* __restrict__ gnw,
                                              const float* __restrict__ gnb) {
    extern __shared__ float s_t[];          // [TILE][CSTR] = 179520 B
    __shared__ float s_inv[TILE];
    __shared__ float s_mean[NG], s_istd[NG];
    __shared__ float s_gnw[CC], s_gnb[CC];

    int b = blockIdx.z;
    int x0 = blockIdx.x * TW, y0 = blockIdx.y * TH;
    int tx = threadIdx.x, ty = threadIdx.y;
    int tid = ty * TW + tx;

    if (tid < NG) { s_mean[tid] = g_gnm[b*NG+tid]; s_istd[tid] = g_gni[b*NG+tid]; }
    if (tid < CC) { s_gnw[tid] = gnw[tid]; s_gnb[tid] = gnb[tid]; }

    int gp[2];
    #pragma unroll
    for (int j = 0; j < 2; j++) {
        int i = tid + 256*j;
        if (i < TILE) {
            int yy = i / ROWW, xx = i - yy*ROWW;
            gp[j] = refl(y0 + yy - 1)*WW + refl(x0 + xx - 1);
        }
    }
    #pragma unroll
    for (int j = 0; j < 2; j++) {
        int i = tid + 256*j;
        if (i < TILE) s_inv[i] = g_invn[b*PP + gp[j]];
    }

    for (int c0 = 0; c0 < CC; c0 += 4) {
        const float* xb = x + ((size_t)b*CC + c0) * PP;
        #pragma unroll
        for (int j = 0; j < 2; j++) {
            int i = tid + 256*j;
            if (i < TILE) {
                float4 v;
                v.x = xb[gp[j]];
                v.y = xb[PP   + gp[j]];
                v.z = xb[2*PP + gp[j]];
                v.w = xb[3*PP + gp[j]];
                *(float4*)&s_t[(size_t)i*CSTR + c0] = v;
            }
        }
    }
    __syncthreads();

    float dots[9];
    #pragma unroll
    for (int j = 0; j < 9; j++) dots[j] = 0.f;

    for (int c0 = 0; c0 < CC; c0 += 4) {
        float4 t9[9];
        #pragma unroll
        for (int dy = 0; dy < 3; dy++)
            #pragma unroll
            for (int dx = 0; dx < 3; dx++)
                t9[dy*3+dx] = *(float4*)&s_t[(size_t)((ty+dy)*ROWW + tx+dx)*CSTR + c0];
        float4 v = t9[4];
        #pragma unroll
        for (int j = 0; j < 9; j++)
            dots[j] += v.x*t9[j].x + v.y*t9[j].y + v.z*t9[j].z + v.w*t9[j].w;
    }

    float invc = s_inv[(ty+1)*ROWW + tx + 1];
    float sims[9];
    #pragma unroll
    for (int j = 0; j < 9; j++) {
        int dy = j / 3, dx = j - dy*3;
        sims[j] = dots[j] * invc * s_inv[(ty+dy)*ROWW + tx + dx];
    }

    int p = (y0 + ty) * WW + x0 + tx;
    float df = g_df[b*PP + p];
    float mn = g_mnv[b];
    float mx = g_mxv[b];
    float dn = (df - mn) / (mx - mn + 1e-8f);
    int k = 1 + (int)rintf(dn * 7.f);
    if (k < 1) k = 1; if (k > 8) k = 8;

    float sv[9]; int si[9];
    #pragma unroll
    for (int j = 0; j < 9; j++) { sv[j] = sims[j]; si[j] = j; }
    CE(0,3); CE(1,7); CE(2,5); CE(4,8);
    CE(0,7); CE(2,4); CE(3,8); CE(5,6);
    CE(0,2); CE(1,3); CE(4,5); CE(7,8);
    CE(1,4); CE(3,6); CE(5,7);
    CE(0,1); CE(2,4); CE(3,5); CE(6,8);
    CE(2,3); CE(4,5); CE(6,7);
    CE(1,2); CE(3,4); CE(5,6);

    float ts = sv[0]; int tix = si[0];
    #pragma unroll
    for (int r = 0; r < 9; r++) { if (r == k-1) { ts = sv[r]; tix = si[r]; } }

    float wj[9]; float ws = 0.f;
    #pragma unroll
    for (int j = 0; j < 9; j++) {
        bool sel = (sims[j] > ts) || (sims[j] == ts && j <= tix);
        wj[j] = sel ? expf(sims[j]) : 0.f;
        ws += wj[j];
    }
    float iws = 1.f / ws;
    #pragma unroll
    for (int j = 0; j < 9; j++) wj[j] *= iws;

    for (int c0 = 0; c0 < CC; c0 += 4) {
        float4 t9[9];
        #pragma unroll
        for (int dy = 0; dy < 3; dy++)
            #pragma unroll
            for (int dx = 0; dx < 3; dx++)
                t9[dy*3+dx] = *(float4*)&s_t[(size_t)((ty+dy)*ROWW + tx+dx)*CSTR + c0];
        float4 acc = make_float4(0.f, 0.f, 0.f, 0.f);
        #pragma unroll
        for (int j = 0; j < 9; j++) {
            acc.x += wj[j]*t9[j].x; acc.y += wj[j]*t9[j].y;
            acc.z += wj[j]*t9[j].z; acc.w += wj[j]*t9[j].w;
        }
        float4 ctr = t9[4];
        int g = c0 >> 3;
        float gm = s_mean[g], gi = s_istd[g];
        float* dst = &g_enh[(size_t)(b*CC + c0) * PP + p];
        dst[0]     = acc.x + (ctr.x - gm)*gi*s_gnw[c0]   + s_gnb[c0];
        dst[PP]    = acc.y + (ctr.y - gm)*gi*s_gnw[c0+1] + s_gnb[c0+1];
        dst[2*PP]  = acc.z + (ctr.z - gm)*gi*s_gnw[c0+2] + s_gnb[c0+2];
        dst[3*PP]  = acc.w + (ctr.w - gm)*gi*s_gnw[c0+3] + s_gnb[c0+3];
    }
}

// ---------------- K5: fused FFN, NT=64 pixels per CTA, occupancy 2 -----------
#define NT 64
#define ESTR 68      // words per n-row of Es (K=128 -> 64 words + 4 pad)
#define HSTR 132     // words per n-row of Hs (K=256 -> 128 words + 4 pad)

#define MMA_BF16(C, A, B2) asm volatile( \
    "mma.sync.aligned.m16n8k16.row.col.f32.bf16.bf16.f32 " \
    "{%0,%1,%2,%3}, {%4,%5,%6,%7}, {%8,%9}, {%0,%1,%2,%3};\n" \
    : "+f"((C)[0]), "+f"((C)[1]), "+f"((C)[2]), "+f"((C)[3]) \
    : "r"((A)[0]), "r"((A)[1]), "r"((A)[2]), "r"((A)[3]), \
      "r"((B2)[0]), "r"((B2)[1]))

__global__ void __launch_bounds__(256, 2) k_ffn(const float* __restrict__ b1,
                                                const float* __restrict__ b2,
                                                float* __restrict__ out) {
    extern __shared__ unsigned smu[];
    unsigned* Es = smu;                     // [64][ESTR]
    unsigned* Hs = Es + 64*ESTR;            // [64][HSTR]

    int b = blockIdx.y;
    int n0 = blockIdx.x * NT;
    int tid = threadIdx.x;
    int warp = tid >> 5, lane = tid & 31;
    int lm = lane >> 2, lk = lane & 3;

    const float* E = g_enh + (size_t)b * CC * PP + n0;

    // ---- Es fill: E[k][n] fp32 -> bf16x2 pairs along k, n-major layout ----
    #pragma unroll
    for (int j = 0; j < 16; j++) {
        int i = tid + 256*j;                // 0..4095
        int w = i >> 6, n = i & 63;
        float lo = E[(size_t)(2*w)   * PP + n];
        float hi = E[(size_t)(2*w+1) * PP + n];
        Es[n*ESTR + w] = packbf(lo, hi);
    }
    __syncthreads();

    // ---- GEMM1: 8 warps, warp tile 32(M) x 64(N) ----
    int wm1 = warp * 32;
    int m16a = warp * 2;
    float c1[2][8][4];
    #pragma unroll
    for (int mt = 0; mt < 2; mt++)
        #pragma unroll
        for (int nt = 0; nt < 8; nt++)
            #pragma unroll
            for (int q = 0; q < 4; q++) c1[mt][nt][q] = 0.f;

    #pragma unroll
    for (int st = 0; st < 8; st++) {           // 8 k16 steps
        int kw = st * 8;
        unsigned a[2][4], bw[8][2];
        *(uint4*)a[0] = g_w1f[((m16a    )*8 + st)*32 + lane];
        *(uint4*)a[1] = g_w1f[((m16a + 1)*8 + st)*32 + lane];
        #pragma unroll
        for (int nt = 0; nt < 8; nt++) {
            int nc = nt*8 + lm;
            bw[nt][0] = Es[nc*ESTR + kw + lk];
            bw[nt][1] = Es[nc*ESTR + kw + 4 + lk];
        }
        #pragma unroll
        for (int mt = 0; mt < 2; mt++)
            #pragma unroll
            for (int nt = 0; nt < 8; nt++)
                MMA_BF16(c1[mt][nt], a[mt], bw[nt]);
    }

    // ---- H: bias + relu, pack row pairs via shfl, store n-major bf16 ----
    #pragma unroll
    for (int mt = 0; mt < 2; mt++) {
        int mr = wm1 + mt*16 + lm;
        float bi0 = b1[mr], bi1 = b1[mr + 8];
        #pragma unroll
        for (int nt = 0; nt < 8; nt++) {
            float v0 = fmaxf(c1[mt][nt][0] + bi0, 0.f);
            float v1 = fmaxf(c1[mt][nt][1] + bi0, 0.f);
            float v2 = fmaxf(c1[mt][nt][2] + bi1, 0.f);
            float v3 = fmaxf(c1[mt][nt][3] + bi1, 0.f);
            float p0 = __shfl_xor_sync(0xffffffffu, v0, 4);
            float p1 = __shfl_xor_sync(0xffffffffu, v1, 4);
            float p2 = __shfl_xor_sync(0xffffffffu, v2, 4);
            float p3 = __shfl_xor_sync(0xffffffffu, v3, 4);
            if (!(lm & 1)) {                      // even rows pack (mr, mr+1)
                int colA = nt*8 + 2*lk;
                int w0 = mr >> 1;
                Hs[colA    *HSTR + w0]     = packbf(v0, p0);
                Hs[(colA+1)*HSTR + w0]     = packbf(v1, p1);
                Hs[colA    *HSTR + w0 + 4] = packbf(v2, p2);
                Hs[(colA+1)*HSTR + w0 + 4] = packbf(v3, p3);
            }
        }
    }
    __syncthreads();

    // ---- GEMM2: 8 warps, warp tile 16(M) x 64(N), K=256 ----
    int wm2 = warp * 16;
    int m16b = warp;
    float c2[8][4];
    #pragma unroll
    for (int nt = 0; nt < 8; nt++)
        #pragma unroll
        for (int q = 0; q < 4; q++) c2[nt][q] = 0.f;

    #pragma unroll
    for (int st = 0; st < 16; st++) {          // 16 k16 steps
        int kw = st * 8;
        unsigned a[4], bw[8][2];
        *(uint4*)a = g_w2f[(m16b*16 + st)*32 + lane];
        #pragma unroll
        for (int nt = 0; nt < 8; nt++) {
            int nc = nt*8 + lm;
            bw[nt][0] = Hs[nc*HSTR + kw + lk];
            bw[nt][1] = Hs[nc*HSTR + kw + 4 + lk];
        }
        #pragma unroll
        for (int nt = 0; nt < 8; nt++)
            MMA_BF16(c2[nt], a, bw[nt]);
    }

    // ---- epilogue: out = enhanced + ffn + b2 ----
    {
        int mr = wm2 + lm;
        float bi0 = b2[mr], bi1 = b2[mr + 8];
        #pragma unroll
        for (int nt = 0; nt < 8; nt++) {
            int col = nt*8 + 2*lk;
            size_t o0 = (size_t)(b*CC + mr) * PP + n0 + col;
            size_t o1 = o0 + (size_t)8 * PP;
            float2 e0 = *(const float2*)&g_enh[o0];
            float2 e1 = *(const float2*)&g_enh[o1];
            float2 v0, v1;
            v0.x = c2[nt][0] + bi0 + e0.x;
            v0.y = c2[nt][1] + bi0 + e0.y;
            v1.x = c2[nt][2] + bi1 + e1.x;
            v1.y = c2[nt][3] + bi1 + e1.y;
            *(float2*)&out[o0] = v0;
            *(float2*)&out[o1] = v1;
        }
    }
}

// ---------------- launch ----------------
extern "C" void kernel_launch(void* const* d_in, const int* in_sizes, int n_in,
                              void* d_out, int out_size) {
    const float* x   = (const float*)d_in[0];
    const float* gnw = (const float*)d_in[1];
    const float* gnb = (const float*)d_in[2];
    const float* w1  = (const float*)d_in[3];
    const float* b1  = (const float*)d_in[4];
    const float* w2  = (const float*)d_in[5];
    const float* b2  = (const float*)d_in[6];
    float* out = (float*)d_out;

    const int smem_main = TILE * CSTR * 4;             // 179520 B
    const int smem_ffn  = (64*ESTR + 64*HSTR) * 4;     // 51200 B -> 2 CTAs/SM
    cudaFuncSetAttribute(k_main, cudaFuncAttributeMaxDynamicSharedMemorySize, smem_main);
    cudaFuncSetAttribute(k_ffn,  cudaFuncAttributeMaxDynamicSharedMemorySize, smem_ffn);

    k_stats<<<NBLK + 32, 256>>>(x, w1, w2);            // +32 blocks: W->frag bf16
    k_df   <<<NBLK, 256>>>();
    k_gn   <<<1, 128>>>();
    k_main <<<dim3(WW/TW, HH/TH, BB), dim3(TW, TH), smem_main>>>(x, gnw, gnb);
    k_ffn  <<<dim3(PP/NT, BB), 256, smem_ffn>>>(b1, b2, out);
}

// round 11
// speedup vs baseline: 2.4043x; 1.0693x over previous
#include <cuda_runtime.h>
#include <cuda_bf16.h>
#include <math.h>
#include <stdint.h>

// Problem constants
#define BB 8
#define CC 128
#define HH 96
#define WW 96
#define PP (HH*WW)       // 9216
#define NG 16            // groups
#define CPG 8            // channels per group
#define NBLK 288         // stats/df blocks (BB*PP/256)
#define BPB 36           // blocks per batch (PP/256)

// ---------------- scratch (device globals; no allocs allowed) ----------------
__device__ float g_avg [BB*PP];
__device__ float g_invn[BB*PP];
__device__ float g_df  [BB*PP];
__device__ float g_ps  [NBLK*NG];
__device__ float g_pss [NBLK*NG];
__device__ float g_pmn [NBLK];
__device__ float g_pmx [NBLK];
__device__ float g_gnm [BB*NG];
__device__ float g_gni [BB*NG];
__device__ float g_mnv [BB];
__device__ float g_mxv [BB];
__device__ float g_enh [BB*CC*PP];         // enhanced (out + groupnorm)
__device__ uint4 g_w1f [16*8*32];          // w1 bf16x2 in mma-fragment order
__device__ uint4 g_w2f [8*16*32];          // w2 bf16x2 in mma-fragment order

__device__ __forceinline__ int refl(int i) {
    return i < 0 ? -i : (i >= HH ? 2*HH - 2 - i : i);
}

__device__ __forceinline__ unsigned packbf(float lo, float hi) {
    unsigned d;
    asm("cvt.rn.bf16x2.f32 %0, %1, %2;" : "=r"(d) : "f"(hi), "f"(lo));
    return d;
}

// ---------------- K1: per-pixel avg & inv-norm, per-(b,g) partial sums -------
// blocks >= NBLK convert w1/w2 to bf16x2 fragment layout instead.
__global__ void k_stats(const float* __restrict__ x,
                        const float* __restrict__ w1,
                        const float* __restrict__ w2) {
    int tid = threadIdx.x;
    if (blockIdx.x >= NBLK) {
        int idx = (blockIdx.x - NBLK) * 256 + tid;     // 0..8191
        int lane = idx & 31, lk = lane & 3, lm = lane >> 2;
        int kw;
        if (idx < 4096) {                              // w1: 16 m-groups x 8 steps
            int m16 = idx >> 8, st = (idx >> 5) & 7;
            int mr = m16*16 + lm; kw = st*8;
            uint4 v;
            v.x = packbf(w1[mr*128     + 2*(kw+lk)],   w1[mr*128     + 2*(kw+lk)+1]);
            v.y = packbf(w1[(mr+8)*128 + 2*(kw+lk)],   w1[(mr+8)*128 + 2*(kw+lk)+1]);
            v.z = packbf(w1[mr*128     + 2*(kw+4+lk)], w1[mr*128     + 2*(kw+4+lk)+1]);
            v.w = packbf(w1[(mr+8)*128 + 2*(kw+4+lk)], w1[(mr+8)*128 + 2*(kw+4+lk)+1]);
            g_w1f[idx] = v;
        } else {                                       // w2: 8 m-groups x 16 steps
            int j = idx - 4096;
            int m16 = j >> 9, st = (j >> 5) & 15;
            int mr = m16*16 + lm; kw = st*8;
            uint4 v;
            v.x = packbf(w2[mr*256     + 2*(kw+lk)],   w2[mr*256     + 2*(kw+lk)+1]);
            v.y = packbf(w2[(mr+8)*256 + 2*(kw+lk)],   w2[(mr+8)*256 + 2*(kw+lk)+1]);
            v.z = packbf(w2[mr*256     + 2*(kw+4+lk)], w2[mr*256     + 2*(kw+4+lk)+1]);
            v.w = packbf(w2[(mr+8)*256 + 2*(kw+4+lk)], w2[(mr+8)*256 + 2*(kw+4+lk)+1]);
            g_w2f[j] = v;
        }
        return;
    }

    int idx = blockIdx.x * 256 + tid;        // (b,p)
    int b = idx / PP;
    const float* xb = x + (size_t)b * CC * PP + (idx - b*PP);
    int lane = tid & 31;

    __shared__ float s_gs[NG], s_gss[NG];
    if (tid < NG) { s_gs[tid] = 0.f; s_gss[tid] = 0.f; }
    __syncthreads();

    float sum = 0.f, ssq = 0.f;
    #pragma unroll
    for (int g = 0; g < NG; g++) {
        float gs = 0.f, gss = 0.f;
        #pragma unroll
        for (int cc = 0; cc < CPG; cc++) {
            float v = xb[(size_t)(g*CPG + cc) * PP];
            gs += v; gss += v*v;
        }
        sum += gs; ssq += gss;
        #pragma unroll
        for (int off = 16; off; off >>= 1) {
            gs  += __shfl_xor_sync(0xffffffffu, gs,  off);
            gss += __shfl_xor_sync(0xffffffffu, gss, off);
        }
        if (lane == 0) { atomicAdd(&s_gs[g], gs); atomicAdd(&s_gss[g], gss); }
    }
    __syncthreads();
    if (tid < NG) {
        g_ps [blockIdx.x*NG + tid] = s_gs [tid];
        g_pss[blockIdx.x*NG + tid] = s_gss[tid];
    }
    g_avg [idx] = sum * (1.f/128.f);
    g_invn[idx] = 1.f / fmaxf(sqrtf(ssq), 1e-12f);
}

// ---------------- K2: laplacian of avg (zero pad), per-block min/max ---------
__global__ void k_df() {
    int tid = threadIdx.x;
    int idx = blockIdx.x * 256 + tid;
    int b = idx / PP;
    int p = idx - b*PP;
    int y = p / WW, xq = p - y*WW;
    float c = g_avg[idx];
    float up = (y > 0)      ? g_avg[idx - WW] : 0.f;
    float dn = (y < HH-1)   ? g_avg[idx + WW] : 0.f;
    float lf = (xq > 0)     ? g_avg[idx - 1]  : 0.f;
    float rt = (xq < WW-1)  ? g_avg[idx + 1]  : 0.f;
    float df = fabsf(4.f*c - up - dn - lf - rt);
    g_df[idx] = df;

    __shared__ float smn[256], smx[256];
    smn[tid] = df; smx[tid] = df;
    __syncthreads();
    for (int s = 128; s; s >>= 1) {
        if (tid < s) {
            smn[tid] = fminf(smn[tid], smn[tid+s]);
            smx[tid] = fmaxf(smx[tid], smx[tid+s]);
        }
        __syncthreads();
    }
    if (tid == 0) { g_pmn[blockIdx.x] = smn[0]; g_pmx[blockIdx.x] = smx[0]; }
}

// ---------------- K3: reduce partials -> GN stats + per-batch min/max --------
__global__ void k_gn() {
    int i = threadIdx.x;          // (b,g)
    int b = i >> 4, g = i & 15;
    float s = 0.f, ss = 0.f;
    for (int l = 0; l < BPB; l++) {
        s  += g_ps [(b*BPB + l)*NG + g];
        ss += g_pss[(b*BPB + l)*NG + g];
    }
    const float N = (float)(CPG * PP);
    float mean = s / N;
    float var = ss / N - mean*mean;
    g_gnm[i] = mean;
    g_gni[i] = rsqrtf(var + 1e-5f);

    if (i < BB) {
        float mn = g_pmn[i*BPB], mx = g_pmx[i*BPB];
        for (int l = 1; l < BPB; l++) {
            mn = fminf(mn, g_pmn[i*BPB + l]);
            mx = fmaxf(mx, g_pmx[i*BPB + l]);
        }
        g_mnv[i] = mn; g_mxv[i] = mx;
    }
}

// ---------------- K4: IPG core, TH=4 tile + 8-ch double-buffer streaming -----
#define TW 32
#define TH 4
#define ROWW 34          // TW+2
#define TILE2 204        // (TH+2)*ROWW
#define PSTR 12          // words per position: 8 ch + 4 pad (conflict-free 128b)

#define CE(a_,b_) do { \
    if ((sv[b_] > sv[a_]) || (sv[b_] == sv[a_] && si[b_] < si[a_])) { \
        float t_ = sv[a_]; sv[a_] = sv[b_]; sv[b_] = t_; \
        int u_ = si[a_]; si[a_] = si[b_]; si[b_] = u_; } \
} while (0)

__global__ void __launch_bounds__(128) k_main(const float* __restrict__ x,
                                              const float* __restrict__ gnw,
                                              const float* __restrict__ gnb) {
    __shared__ float s_t[2][TILE2*PSTR];    // 2 x 9792 B
    __shared__ float s_inv[TILE2];
    __shared__ float s_mean[NG], s_istd[NG];
    __shared__ float s_gnw[CC], s_gnb[CC];

    int b = blockIdx.z;
    int x0 = blockIdx.x * TW, y0 = blockIdx.y * TH;
    int tx = threadIdx.x, ty = threadIdx.y;
    int tid = ty * TW + tx;

    if (tid < NG) { s_mean[tid] = g_gnm[b*NG+tid]; s_istd[tid] = g_gni[b*NG+tid]; }
    s_gnw[tid] = gnw[tid]; s_gnb[tid] = gnb[tid];

    // reflected global offsets for this thread's (up to 2) fill positions
    int gp[2];
    #pragma unroll
    for (int j = 0; j < 2; j++) {
        int i = tid + 128*j;
        if (i < TILE2) {
            int yy = i / ROWW, xx = i - yy*ROWW;
            gp[j] = refl(y0 + yy - 1)*WW + refl(x0 + xx - 1);
        }
    }
    #pragma unroll
    for (int j = 0; j < 2; j++) {
        int i = tid + 128*j;
        if (i < TILE2) s_inv[i] = g_invn[b*PP + gp[j]];
    }

    const float* xbase = x + (size_t)b * CC * PP;

    // prefetch registers: 2 positions x 8 channels
    float pv[2][8];
    auto ldchunk = [&](int ch) {
        const float* xb = xbase + (size_t)(ch*8) * PP;
        #pragma unroll
        for (int j = 0; j < 2; j++) {
            int i = tid + 128*j;
            if (i < TILE2) {
                #pragma unroll
                for (int c = 0; c < 8; c++) pv[j][c] = xb[(size_t)c*PP + gp[j]];
            }
        }
    };
    auto stchunk = [&](int buf) {
        #pragma unroll
        for (int j = 0; j < 2; j++) {
            int i = tid + 128*j;
            if (i < TILE2) {
                float4 a = make_float4(pv[j][0], pv[j][1], pv[j][2], pv[j][3]);
                float4 c4 = make_float4(pv[j][4], pv[j][5], pv[j][6], pv[j][7]);
                *(float4*)&s_t[buf][i*PSTR]     = a;
                *(float4*)&s_t[buf][i*PSTR + 4] = c4;
            }
        }
    };

    int base9[9];
    #pragma unroll
    for (int dy = 0; dy < 3; dy++)
        #pragma unroll
        for (int dx = 0; dx < 3; dx++)
            base9[dy*3+dx] = ((ty+dy)*ROWW + tx+dx)*PSTR;

    // ---------------- pass 1: dots ----------------
    float dots[9];
    #pragma unroll
    for (int j = 0; j < 9; j++) dots[j] = 0.f;

    ldchunk(0); stchunk(0);
    __syncthreads();
    for (int ch = 0; ch < 16; ch++) {
        int cur = ch & 1;
        if (ch < 15) ldchunk(ch + 1);
        #pragma unroll
        for (int half = 0; half < 2; half++) {
            float4 t9[9];
            #pragma unroll
            for (int j = 0; j < 9; j++)
                t9[j] = *(float4*)&s_t[cur][base9[j] + half*4];
            float4 v = t9[4];
            #pragma unroll
            for (int j = 0; j < 9; j++)
                dots[j] += v.x*t9[j].x + v.y*t9[j].y + v.z*t9[j].z + v.w*t9[j].w;
        }
        if (ch < 15) stchunk(cur ^ 1);
        __syncthreads();
    }

    float invc = s_inv[(ty+1)*ROWW + tx + 1];
    float sims[9];
    #pragma unroll
    for (int j = 0; j < 9; j++) {
        int dy = j / 3, dx = j - dy*3;
        sims[j] = dots[j] * invc * s_inv[(ty+dy)*ROWW + tx + dx];
    }

    int p = (y0 + ty) * WW + x0 + tx;
    float df = g_df[b*PP + p];
    float mn = g_mnv[b];
    float mx = g_mxv[b];
    float dn = (df - mn) / (mx - mn + 1e-8f);
    int k = 1 + (int)rintf(dn * 7.f);
    if (k < 1) k = 1; if (k > 8) k = 8;

    float sv[9]; int si[9];
    #pragma unroll
    for (int j = 0; j < 9; j++) { sv[j] = sims[j]; si[j] = j; }
    CE(0,3); CE(1,7); CE(2,5); CE(4,8);
    CE(0,7); CE(2,4); CE(3,8); CE(5,6);
    CE(0,2); CE(1,3); CE(4,5); CE(7,8);
    CE(1,4); CE(3,6); CE(5,7);
    CE(0,1); CE(2,4); CE(3,5); CE(6,8);
    CE(2,3); CE(4,5); CE(6,7);
    CE(1,2); CE(3,4); CE(5,6);

    float ts = sv[0]; int tix = si[0];
    #pragma unroll
    for (int r = 0; r < 9; r++) { if (r == k-1) { ts = sv[r]; tix = si[r]; } }

    float wj[9]; float ws = 0.f;
    #pragma unroll
    for (int j = 0; j < 9; j++) {
        bool sel = (sims[j] > ts) || (sims[j] == ts && j <= tix);
        wj[j] = sel ? expf(sims[j]) : 0.f;
        ws += wj[j];
    }
    float iws = 1.f / ws;
    #pragma unroll
    for (int j = 0; j < 9; j++) wj[j] *= iws;

    // ---------------- pass 2: weighted sum + groupnorm -> enhanced -----------
    ldchunk(0); stchunk(0);
    __syncthreads();
    for (int ch = 0; ch < 16; ch++) {
        int cur = ch & 1;
        if (ch < 15) ldchunk(ch + 1);
        float gm = s_mean[ch], gi = s_istd[ch];     // group == chunk (CPG==8)
        #pragma unroll
        for (int half = 0; half < 2; half++) {
            float4 t9[9];
            #pragma unroll
            for (int j = 0; j < 9; j++)
                t9[j] = *(float4*)&s_t[cur][base9[j] + half*4];
            float4 acc = make_float4(0.f, 0.f, 0.f, 0.f);
            #pragma unroll
            for (int j = 0; j < 9; j++) {
                acc.x += wj[j]*t9[j].x; acc.y += wj[j]*t9[j].y;
                acc.z += wj[j]*t9[j].z; acc.w += wj[j]*t9[j].w;
            }
            float4 ctr = t9[4];
            int c = ch*8 + half*4;
            float* dst = &g_enh[(size_t)(b*CC + c) * PP + p];
            dst[0]    = acc.x + (ctr.x - gm)*gi*s_gnw[c]   + s_gnb[c];
            dst[PP]   = acc.y + (ctr.y - gm)*gi*s_gnw[c+1] + s_gnb[c+1];
            dst[2*PP] = acc.z + (ctr.z - gm)*gi*s_gnw[c+2] + s_gnb[c+2];
            dst[3*PP] = acc.w + (ctr.w - gm)*gi*s_gnw[c+3] + s_gnb[c+3];
        }
        if (ch < 15) stchunk(cur ^ 1);
        __syncthreads();
    }
}

// ---------------- K5: fused FFN, NT=64 pixels per CTA, occupancy 2 -----------
#define NT 64
#define ESTR 68      // words per n-row of Es (K=128 -> 64 words + 4 pad)
#define HSTR 132     // words per n-row of Hs (K=256 -> 128 words + 4 pad)

#define MMA_BF16(C, A, B2) asm volatile( \
    "mma.sync.aligned.m16n8k16.row.col.f32.bf16.bf16.f32 " \
    "{%0,%1,%2,%3}, {%4,%5,%6,%7}, {%8,%9}, {%0,%1,%2,%3};\n" \
    : "+f"((C)[0]), "+f"((C)[1]), "+f"((C)[2]), "+f"((C)[3]) \
    : "r"((A)[0]), "r"((A)[1]), "r"((A)[2]), "r"((A)[3]), \
      "r"((B2)[0]), "r"((B2)[1]))

__global__ void __launch_bounds__(256, 2) k_ffn(const float* __restrict__ b1,
                                                const float* __restrict__ b2,
                                                float* __restrict__ out) {
    extern __shared__ unsigned smu[];
    unsigned* Es = smu;                     // [64][ESTR]
    unsigned* Hs = Es + 64*ESTR;            // [64][HSTR]

    int b = blockIdx.y;
    int n0 = blockIdx.x * NT;
    int tid = threadIdx.x;
    int warp = tid >> 5, lane = tid & 31;
    int lm = lane >> 2, lk = lane & 3;

    const float* E = g_enh + (size_t)b * CC * PP + n0;

    // ---- Es fill: E[k][n] fp32 -> bf16x2 pairs along k, n-major layout ----
    #pragma unroll
    for (int j = 0; j < 16; j++) {
        int i = tid + 256*j;                // 0..4095
        int w = i >> 6, n = i & 63;
        float lo = E[(size_t)(2*w)   * PP + n];
        float hi = E[(size_t)(2*w+1) * PP + n];
        Es[n*ESTR + w] = packbf(lo, hi);
    }
    __syncthreads();

    // ---- GEMM1: 8 warps, warp tile 32(M) x 64(N) ----
    int wm1 = warp * 32;
    int m16a = warp * 2;
    float c1[2][8][4];
    #pragma unroll
    for (int mt = 0; mt < 2; mt++)
        #pragma unroll
        for (int nt = 0; nt < 8; nt++)
            #pragma unroll
            for (int q = 0; q < 4; q++) c1[mt][nt][q] = 0.f;

    #pragma unroll
    for (int st = 0; st < 8; st++) {           // 8 k16 steps
        int kw = st * 8;
        unsigned a[2][4], bw[8][2];
        *(uint4*)a[0] = g_w1f[((m16a    )*8 + st)*32 + lane];
        *(uint4*)a[1] = g_w1f[((m16a + 1)*8 + st)*32 + lane];
        #pragma unroll
        for (int nt = 0; nt < 8; nt++) {
            int nc = nt*8 + lm;
            bw[nt][0] = Es[nc*ESTR + kw + lk];
            bw[nt][1] = Es[nc*ESTR + kw + 4 + lk];
        }
        #pragma unroll
        for (int mt = 0; mt < 2; mt++)
            #pragma unroll
            for (int nt = 0; nt < 8; nt++)
                MMA_BF16(c1[mt][nt], a[mt], bw[nt]);
    }

    // ---- H: bias + relu, pack row pairs via shfl, store n-major bf16 ----
    #pragma unroll
    for (int mt = 0; mt < 2; mt++) {
        int mr = wm1 + mt*16 + lm;
        float bi0 = b1[mr], bi1 = b1[mr + 8];
        #pragma unroll
        for (int nt = 0; nt < 8; nt++) {
            float v0 = fmaxf(c1[mt][nt][0] + bi0, 0.f);
            float v1 = fmaxf(c1[mt][nt][1] + bi0, 0.f);
            float v2 = fmaxf(c1[mt][nt][2] + bi1, 0.f);
            float v3 = fmaxf(c1[mt][nt][3] + bi1, 0.f);
            float p0 = __shfl_xor_sync(0xffffffffu, v0, 4);
            float p1 = __shfl_xor_sync(0xffffffffu, v1, 4);
            float p2 = __shfl_xor_sync(0xffffffffu, v2, 4);
            float p3 = __shfl_xor_sync(0xffffffffu, v3, 4);
            if (!(lm & 1)) {                      // even rows pack (mr, mr+1)
                int colA = nt*8 + 2*lk;
                int w0 = mr >> 1;
                Hs[colA    *HSTR + w0]     = packbf(v0, p0);
                Hs[(colA+1)*HSTR + w0]     = packbf(v1, p1);
                Hs[colA    *HSTR + w0 + 4] = packbf(v2, p2);
                Hs[(colA+1)*HSTR + w0 + 4] = packbf(v3, p3);
            }
        }
    }
    __syncthreads();

    // ---- GEMM2: 8 warps, warp tile 16(M) x 64(N), K=256 ----
    int wm2 = warp * 16;
    int m16b = warp;
    float c2[8][4];
    #pragma unroll
    for (int nt = 0; nt < 8; nt++)
        #pragma unroll
        for (int q = 0; q < 4; q++) c2[nt][q] = 0.f;

    #pragma unroll
    for (int st = 0; st < 16; st++) {          // 16 k16 steps
        int kw = st * 8;
        unsigned a[4], bw[8][2];
        *(uint4*)a = g_w2f[(m16b*16 + st)*32 + lane];
        #pragma unroll
        for (int nt = 0; nt < 8; nt++) {
            int nc = nt*8 + lm;
            bw[nt][0] = Hs[nc*HSTR + kw + lk];
            bw[nt][1] = Hs[nc*HSTR + kw + 4 + lk];
        }
        #pragma unroll
        for (int nt = 0; nt < 8; nt++)
            MMA_BF16(c2[nt], a, bw[nt]);
    }

    // ---- epilogue: out = enhanced + ffn + b2 ----
    {
        int mr = wm2 + lm;
        float bi0 = b2[mr], bi1 = b2[mr + 8];
        #pragma unroll
        for (int nt = 0; nt < 8; nt++) {
            int col = nt*8 + 2*lk;
            size_t o0 = (size_t)(b*CC + mr) * PP + n0 + col;
            size_t o1 = o0 + (size_t)8 * PP;
            float2 e0 = *(const float2*)&g_enh[o0];
            float2 e1 = *(const float2*)&g_enh[o1];
            float2 v0, v1;
            v0.x = c2[nt][0] + bi0 + e0.x;
            v0.y = c2[nt][1] + bi0 + e0.y;
            v1.x = c2[nt][2] + bi1 + e1.x;
            v1.y = c2[nt][3] + bi1 + e1.y;
            *(float2*)&out[o0] = v0;
            *(float2*)&out[o1] = v1;
        }
    }
}

// ---------------- launch ----------------
extern "C" void kernel_launch(void* const* d_in, const int* in_sizes, int n_in,
                              void* d_out, int out_size) {
    const float* x   = (const float*)d_in[0];
    const float* gnw = (const float*)d_in[1];
    const float* gnb = (const float*)d_in[2];
    const float* w1  = (const float*)d_in[3];
    const float* b1  = (const float*)d_in[4];
    const float* w2  = (const float*)d_in[5];
    const float* b2  = (const float*)d_in[6];
    float* out = (float*)d_out;

    const int smem_ffn = (64*ESTR + 64*HSTR) * 4;      // 51200 B -> 2 CTAs/SM
    cudaFuncSetAttribute(k_ffn, cudaFuncAttributeMaxDynamicSharedMemorySize, smem_ffn);

    k_stats<<<NBLK + 32, 256>>>(x, w1, w2);            // +32 blocks: W->frag bf16
    k_df   <<<NBLK, 256>>>();
    k_gn   <<<1, 128>>>();
    k_main <<<dim3(WW/TW, HH/TH, BB), dim3(TW, TH)>>>(x, gnw, gnb);
    k_ffn  <<<dim3(PP/NT, BB), 256, smem_ffn>>>(b1, b2, out);
}

// round 12
// speedup vs baseline: 2.4614x; 1.0237x over previous
#include <cuda_runtime.h>
#include <cuda_bf16.h>
#include <math.h>
#include <stdint.h>

// Problem constants
#define BB 8
#define CC 128
#define HH 96
#define WW 96
#define PP (HH*WW)       // 9216
#define NG 16            // groups
#define CPG 8            // channels per group
#define NBLK 288         // stats/df blocks (BB*PP/256)
#define BPB 36           // blocks per batch (PP/256)

// ---------------- scratch (device globals; no allocs allowed) ----------------
__device__ float g_avg [BB*PP];
__device__ float g_invn[BB*PP];
__device__ float g_df  [BB*PP];
__device__ float g_ps  [NBLK*NG];
__device__ float g_pss [NBLK*NG];
__device__ float g_pmn [NBLK];
__device__ float g_pmx [NBLK];
__device__ float g_gnm [BB*NG];
__device__ float g_gni [BB*NG];
__device__ float g_mnv [BB];
__device__ float g_mxv [BB];
__device__ float g_enh [BB*CC*PP];         // enhanced (out + groupnorm)
__device__ uint4 g_w1f [16*8*32];          // w1 bf16x2 in mma-fragment order
__device__ uint4 g_w2f [8*16*32];          // w2 bf16x2 in mma-fragment order

__device__ __forceinline__ int refl(int i) {
    return i < 0 ? -i : (i >= HH ? 2*HH - 2 - i : i);
}

__device__ __forceinline__ unsigned packbf(float lo, float hi) {
    unsigned d;
    asm("cvt.rn.bf16x2.f32 %0, %1, %2;" : "=r"(d) : "f"(hi), "f"(lo));
    return d;
}

// ---------------- K1: per-pixel avg & inv-norm, per-(b,g) partial sums -------
// blocks >= NBLK convert w1/w2 to bf16x2 fragment layout instead.
__global__ void k_stats(const float* __restrict__ x,
                        const float* __restrict__ w1,
                        const float* __restrict__ w2) {
    int tid = threadIdx.x;
    if (blockIdx.x >= NBLK) {
        int idx = (blockIdx.x - NBLK) * 256 + tid;     // 0..8191
        int lane = idx & 31, lk = lane & 3, lm = lane >> 2;
        int kw;
        if (idx < 4096) {                              // w1: 16 m-groups x 8 steps
            int m16 = idx >> 8, st = (idx >> 5) & 7;
            int mr = m16*16 + lm; kw = st*8;
            uint4 v;
            v.x = packbf(w1[mr*128     + 2*(kw+lk)],   w1[mr*128     + 2*(kw+lk)+1]);
            v.y = packbf(w1[(mr+8)*128 + 2*(kw+lk)],   w1[(mr+8)*128 + 2*(kw+lk)+1]);
            v.z = packbf(w1[mr*128     + 2*(kw+4+lk)], w1[mr*128     + 2*(kw+4+lk)+1]);
            v.w = packbf(w1[(mr+8)*128 + 2*(kw+4+lk)], w1[(mr+8)*128 + 2*(kw+4+lk)+1]);
            g_w1f[idx] = v;
        } else {                                       // w2: 8 m-groups x 16 steps
            int j = idx - 4096;
            int m16 = j >> 9, st = (j >> 5) & 15;
            int mr = m16*16 + lm; kw = st*8;
            uint4 v;
            v.x = packbf(w2[mr*256     + 2*(kw+lk)],   w2[mr*256     + 2*(kw+lk)+1]);
            v.y = packbf(w2[(mr+8)*256 + 2*(kw+lk)],   w2[(mr+8)*256 + 2*(kw+lk)+1]);
            v.z = packbf(w2[mr*256     + 2*(kw+4+lk)], w2[mr*256     + 2*(kw+4+lk)+1]);
            v.w = packbf(w2[(mr+8)*256 + 2*(kw+4+lk)], w2[(mr+8)*256 + 2*(kw+4+lk)+1]);
            g_w2f[j] = v;
        }
        return;
    }

    int idx = blockIdx.x * 256 + tid;        // (b,p)
    int b = idx / PP;
    const float* xb = x + (size_t)b * CC * PP + (idx - b*PP);
    int lane = tid & 31;

    __shared__ float s_gs[NG], s_gss[NG];
    if (tid < NG) { s_gs[tid] = 0.f; s_gss[tid] = 0.f; }
    __syncthreads();

    float sum = 0.f, ssq = 0.f;
    #pragma unroll
    for (int g = 0; g < NG; g++) {
        float gs = 0.f, gss = 0.f;
        #pragma unroll
        for (int cc = 0; cc < CPG; cc++) {
            float v = xb[(size_t)(g*CPG + cc) * PP];
            gs += v; gss += v*v;
        }
        sum += gs; ssq += gss;
        #pragma unroll
        for (int off = 16; off; off >>= 1) {
            gs  += __shfl_xor_sync(0xffffffffu, gs,  off);
            gss += __shfl_xor_sync(0xffffffffu, gss, off);
        }
        if (lane == 0) { atomicAdd(&s_gs[g], gs); atomicAdd(&s_gss[g], gss); }
    }
    __syncthreads();
    if (tid < NG) {
        g_ps [blockIdx.x*NG + tid] = s_gs [tid];
        g_pss[blockIdx.x*NG + tid] = s_gss[tid];
    }
    g_avg [idx] = sum * (1.f/128.f);
    g_invn[idx] = 1.f / fmaxf(sqrtf(ssq), 1e-12f);
}

// ---------------- K2: laplacian of avg (zero pad), per-block min/max ---------
__global__ void k_df() {
    int tid = threadIdx.x;
    int idx = blockIdx.x * 256 + tid;
    int b = idx / PP;
    int p = idx - b*PP;
    int y = p / WW, xq = p - y*WW;
    float c = g_avg[idx];
    float up = (y > 0)      ? g_avg[idx - WW] : 0.f;
    float dn = (y < HH-1)   ? g_avg[idx + WW] : 0.f;
    float lf = (xq > 0)     ? g_avg[idx - 1]  : 0.f;
    float rt = (xq < WW-1)  ? g_avg[idx + 1]  : 0.f;
    float df = fabsf(4.f*c - up - dn - lf - rt);
    g_df[idx] = df;

    __shared__ float smn[256], smx[256];
    smn[tid] = df; smx[tid] = df;
    __syncthreads();
    for (int s = 128; s; s >>= 1) {
        if (tid < s) {
            smn[tid] = fminf(smn[tid], smn[tid+s]);
            smx[tid] = fmaxf(smx[tid], smx[tid+s]);
        }
        __syncthreads();
    }
    if (tid == 0) { g_pmn[blockIdx.x] = smn[0]; g_pmx[blockIdx.x] = smx[0]; }
}

// ---------------- K3: reduce partials -> GN stats + per-batch min/max --------
__global__ void k_gn() {
    int i = threadIdx.x;          // (b,g)
    int b = i >> 4, g = i & 15;
    float s = 0.f, ss = 0.f;
    for (int l = 0; l < BPB; l++) {
        s  += g_ps [(b*BPB + l)*NG + g];
        ss += g_pss[(b*BPB + l)*NG + g];
    }
    const float N = (float)(CPG * PP);
    float mean = s / N;
    float var = ss / N - mean*mean;
    g_gnm[i] = mean;
    g_gni[i] = rsqrtf(var + 1e-5f);

    if (i < BB) {
        float mn = g_pmn[i*BPB], mx = g_pmx[i*BPB];
        for (int l = 1; l < BPB; l++) {
            mn = fminf(mn, g_pmn[i*BPB + l]);
            mx = fmaxf(mx, g_pmx[i*BPB + l]);
        }
        g_mnv[i] = mn; g_mxv[i] = mx;
    }
}

// ---------------- K4: IPG core, 2 threads/pixel (channel halves) -------------
#define TW 32
#define TH 4
#define ROWW 34          // TW+2
#define TILE2 204        // (TH+2)*ROWW
#define PSTR 12          // words per position: 8 ch + 4 pad (conflict-free 128b)
#define NPIX 128         // pixels per CTA

#define CE(a_,b_) do { \
    if ((sv[b_] > sv[a_]) || (sv[b_] == sv[a_] && si[b_] < si[a_])) { \
        float t_ = sv[a_]; sv[a_] = sv[b_]; sv[b_] = t_; \
        int u_ = si[a_]; si[a_] = si[b_]; si[b_] = u_; } \
} while (0)

__global__ void __launch_bounds__(256) k_main(const float* __restrict__ x,
                                              const float* __restrict__ gnw,
                                              const float* __restrict__ gnb) {
    __shared__ float s_t[2][2][TILE2*PSTR]; // [half][buf] 4 x 9792 B
    __shared__ float s_red[NPIX][10];       // dot exchange (9 used)
    __shared__ float s_inv[TILE2];
    __shared__ float s_mean[NG], s_istd[NG];
    __shared__ float s_gnw[CC], s_gnb[CC];

    int b = blockIdx.z;
    int x0 = blockIdx.x * TW, y0 = blockIdx.y * TH;
    int tx = threadIdx.x, ty = threadIdx.y, zz = threadIdx.z;
    int tid = ty * TW + tx;                 // pixel 0..127
    int ft  = zz * NPIX + tid;              // flat 0..255

    if (ft < NG) { s_mean[ft] = g_gnm[b*NG+ft]; s_istd[ft] = g_gni[b*NG+ft]; }
    if (ft < CC) { s_gnw[ft] = gnw[ft]; s_gnb[ft] = gnb[ft]; }

    // reflected global offsets for this half's fill positions
    int gp[2];
    #pragma unroll
    for (int j = 0; j < 2; j++) {
        int i = tid + NPIX*j;
        if (i < TILE2) {
            int yy = i / ROWW, xx = i - yy*ROWW;
            gp[j] = refl(y0 + yy - 1)*WW + refl(x0 + xx - 1);
        }
    }
    if (zz == 0) {
        #pragma unroll
        for (int j = 0; j < 2; j++) {
            int i = tid + NPIX*j;
            if (i < TILE2) s_inv[i] = g_invn[b*PP + gp[j]];
        }
    }

    const float* xbase = x + (size_t)(b*CC + zz*64) * PP;  // this half's channels

    float pv[2][8];
    auto ldchunk = [&](int ch) {
        const float* xb = xbase + (size_t)(ch*8) * PP;
        #pragma unroll
        for (int j = 0; j < 2; j++) {
            int i = tid + NPIX*j;
            if (i < TILE2) {
                #pragma unroll
                for (int c = 0; c < 8; c++) pv[j][c] = xb[(size_t)c*PP + gp[j]];
            }
        }
    };
    auto stchunk = [&](int buf) {
        #pragma unroll
        for (int j = 0; j < 2; j++) {
            int i = tid + NPIX*j;
            if (i < TILE2) {
                float4 a  = make_float4(pv[j][0], pv[j][1], pv[j][2], pv[j][3]);
                float4 c4 = make_float4(pv[j][4], pv[j][5], pv[j][6], pv[j][7]);
                *(float4*)&s_t[zz][buf][i*PSTR]     = a;
                *(float4*)&s_t[zz][buf][i*PSTR + 4] = c4;
            }
        }
    };

    int base9[9];
    #pragma unroll
    for (int dy = 0; dy < 3; dy++)
        #pragma unroll
        for (int dx = 0; dx < 3; dx++)
            base9[dy*3+dx] = ((ty+dy)*ROWW + tx+dx)*PSTR;

    // ---------------- pass 1: partial dots over this half's 64 channels ------
    float dots[9];
    #pragma unroll
    for (int j = 0; j < 9; j++) dots[j] = 0.f;

    ldchunk(0); stchunk(0);
    __syncthreads();
    for (int ch = 0; ch < 8; ch++) {
        int cur = ch & 1;
        if (ch < 7) ldchunk(ch + 1);
        #pragma unroll
        for (int half = 0; half < 2; half++) {
            float4 t9[9];
            #pragma unroll
            for (int j = 0; j < 9; j++)
                t9[j] = *(float4*)&s_t[zz][cur][base9[j] + half*4];
            float4 v = t9[4];
            #pragma unroll
            for (int j = 0; j < 9; j++)
                dots[j] += v.x*t9[j].x + v.y*t9[j].y + v.z*t9[j].z + v.w*t9[j].w;
        }
        if (ch < 7) stchunk(cur ^ 1);
        __syncthreads();
    }

    // combine halves: z1 partial -> z0 sums -> full dots broadcast back
    if (zz == 1) {
        #pragma unroll
        for (int j = 0; j < 9; j++) s_red[tid][j] = dots[j];
    }
    __syncthreads();
    if (zz == 0) {
        #pragma unroll
        for (int j = 0; j < 9; j++) { dots[j] += s_red[tid][j]; s_red[tid][j] = dots[j]; }
    }
    __syncthreads();
    if (zz == 1) {
        #pragma unroll
        for (int j = 0; j < 9; j++) dots[j] = s_red[tid][j];
    }

    float invc = s_inv[(ty+1)*ROWW + tx + 1];
    float sims[9];
    #pragma unroll
    for (int j = 0; j < 9; j++) {
        int dy = j / 3, dx = j - dy*3;
        sims[j] = dots[j] * invc * s_inv[(ty+dy)*ROWW + tx + dx];
    }

    int p = (y0 + ty) * WW + x0 + tx;
    float df = g_df[b*PP + p];
    float mn = g_mnv[b];
    float mx = g_mxv[b];
    float dn = (df - mn) / (mx - mn + 1e-8f);
    int k = 1 + (int)rintf(dn * 7.f);
    if (k < 1) k = 1; if (k > 8) k = 8;

    float sv[9]; int si[9];
    #pragma unroll
    for (int j = 0; j < 9; j++) { sv[j] = sims[j]; si[j] = j; }
    CE(0,3); CE(1,7); CE(2,5); CE(4,8);
    CE(0,7); CE(2,4); CE(3,8); CE(5,6);
    CE(0,2); CE(1,3); CE(4,5); CE(7,8);
    CE(1,4); CE(3,6); CE(5,7);
    CE(0,1); CE(2,4); CE(3,5); CE(6,8);
    CE(2,3); CE(4,5); CE(6,7);
    CE(1,2); CE(3,4); CE(5,6);

    float ts = sv[0]; int tix = si[0];
    #pragma unroll
    for (int r = 0; r < 9; r++) { if (r == k-1) { ts = sv[r]; tix = si[r]; } }

    float wj[9]; float ws = 0.f;
    #pragma unroll
    for (int j = 0; j < 9; j++) {
        bool sel = (sims[j] > ts) || (sims[j] == ts && j <= tix);
        wj[j] = sel ? expf(sims[j]) : 0.f;
        ws += wj[j];
    }
    float iws = 1.f / ws;
    #pragma unroll
    for (int j = 0; j < 9; j++) wj[j] *= iws;

    // ---------------- pass 2: weighted sum + groupnorm on this half ----------
    ldchunk(0); stchunk(0);
    __syncthreads();
    for (int ch = 0; ch < 8; ch++) {
        int cur = ch & 1;
        if (ch < 7) ldchunk(ch + 1);
        int gidx = zz*8 + ch;                        // group == global chunk
        float gm = s_mean[gidx], gi = s_istd[gidx];
        #pragma unroll
        for (int half = 0; half < 2; half++) {
            float4 t9[9];
            #pragma unroll
            for (int j = 0; j < 9; j++)
                t9[j] = *(float4*)&s_t[zz][cur][base9[j] + half*4];
            float4 acc = make_float4(0.f, 0.f, 0.f, 0.f);
            #pragma unroll
            for (int j = 0; j < 9; j++) {
                acc.x += wj[j]*t9[j].x; acc.y += wj[j]*t9[j].y;
                acc.z += wj[j]*t9[j].z; acc.w += wj[j]*t9[j].w;
            }
            float4 ctr = t9[4];
            int c = zz*64 + ch*8 + half*4;
            float* dst = &g_enh[(size_t)(b*CC + c) * PP + p];
            dst[0]    = acc.x + (ctr.x - gm)*gi*s_gnw[c]   + s_gnb[c];
            dst[PP]   = acc.y + (ctr.y - gm)*gi*s_gnw[c+1] + s_gnb[c+1];
            dst[2*PP] = acc.z + (ctr.z - gm)*gi*s_gnw[c+2] + s_gnb[c+2];
            dst[3*PP] = acc.w + (ctr.w - gm)*gi*s_gnw[c+3] + s_gnb[c+3];
        }
        if (ch < 7) stchunk(cur ^ 1);
        __syncthreads();
    }
}

// ---------------- K5: fused FFN, NT=64 pixels per CTA, occupancy 2 -----------
#define NT 64
#define ESTR 68      // words per n-row of Es (K=128 -> 64 words + 4 pad)
#define HSTR 132     // words per n-row of Hs (K=256 -> 128 words + 4 pad)

#define MMA_BF16(C, A, B2) asm volatile( \
    "mma.sync.aligned.m16n8k16.row.col.f32.bf16.bf16.f32 " \
    "{%0,%1,%2,%3}, {%4,%5,%6,%7}, {%8,%9}, {%0,%1,%2,%3};\n" \
    : "+f"((C)[0]), "+f"((C)[1]), "+f"((C)[2]), "+f"((C)[3]) \
    : "r"((A)[0]), "r"((A)[1]), "r"((A)[2]), "r"((A)[3]), \
      "r"((B2)[0]), "r"((B2)[1]))

__global__ void __launch_bounds__(256, 2) k_ffn(const float* __restrict__ b1,
                                                const float* __restrict__ b2,
                                                float* __restrict__ out) {
    extern __shared__ unsigned smu[];
    unsigned* Es = smu;                     // [64][ESTR]
    unsigned* Hs = Es + 64*ESTR;            // [64][HSTR]

    int b = blockIdx.y;
    int n0 = blockIdx.x * NT;
    int tid = threadIdx.x;
    int warp = tid >> 5, lane = tid & 31;
    int lm = lane >> 2, lk = lane & 3;

    const float* E = g_enh + (size_t)b * CC * PP + n0;

    // ---- Es fill: E[k][n] fp32 -> bf16x2 pairs along k, n-major layout ----
    #pragma unroll
    for (int j = 0; j < 16; j++) {
        int i = tid + 256*j;                // 0..4095
        int w = i >> 6, n = i & 63;
        float lo = E[(size_t)(2*w)   * PP + n];
        float hi = E[(size_t)(2*w+1) * PP + n];
        Es[n*ESTR + w] = packbf(lo, hi);
    }
    __syncthreads();

    // ---- GEMM1: 8 warps, warp tile 32(M) x 64(N) ----
    int wm1 = warp * 32;
    int m16a = warp * 2;
    float c1[2][8][4];
    #pragma unroll
    for (int mt = 0; mt < 2; mt++)
        #pragma unroll
        for (int nt = 0; nt < 8; nt++)
            #pragma unroll
            for (int q = 0; q < 4; q++) c1[mt][nt][q] = 0.f;

    #pragma unroll
    for (int st = 0; st < 8; st++) {           // 8 k16 steps
        int kw = st * 8;
        unsigned a[2][4], bw[8][2];
        *(uint4*)a[0] = g_w1f[((m16a    )*8 + st)*32 + lane];
        *(uint4*)a[1] = g_w1f[((m16a + 1)*8 + st)*32 + lane];
        #pragma unroll
        for (int nt = 0; nt < 8; nt++) {
            int nc = nt*8 + lm;
            bw[nt][0] = Es[nc*ESTR + kw + lk];
            bw[nt][1] = Es[nc*ESTR + kw + 4 + lk];
        }
        #pragma unroll
        for (int mt = 0; mt < 2; mt++)
            #pragma unroll
            for (int nt = 0; nt < 8; nt++)
                MMA_BF16(c1[mt][nt], a[mt], bw[nt]);
    }

    // ---- H: bias + relu, pack row pairs via shfl, store n-major bf16 ----
    #pragma unroll
    for (int mt = 0; mt < 2; mt++) {
        int mr = wm1 + mt*16 + lm;
        float bi0 = b1[mr], bi1 = b1[mr + 8];
        #pragma unroll
        for (int nt = 0; nt < 8; nt++) {
            float v0 = fmaxf(c1[mt][nt][0] + bi0, 0.f);
            float v1 = fmaxf(c1[mt][nt][1] + bi0, 0.f);
            float v2 = fmaxf(c1[mt][nt][2] + bi1, 0.f);
            float v3 = fmaxf(c1[mt][nt][3] + bi1, 0.f);
            float p0 = __shfl_xor_sync(0xffffffffu, v0, 4);
            float p1 = __shfl_xor_sync(0xffffffffu, v1, 4);
            float p2 = __shfl_xor_sync(0xffffffffu, v2, 4);
            float p3 = __shfl_xor_sync(0xffffffffu, v3, 4);
            if (!(lm & 1)) {                      // even rows pack (mr, mr+1)
                int colA = nt*8 + 2*lk;
                int w0 = mr >> 1;
                Hs[colA    *HSTR + w0]     = packbf(v0, p0);
                Hs[(colA+1)*HSTR + w0]     = packbf(v1, p1);
                Hs[colA    *HSTR + w0 + 4] = packbf(v2, p2);
                Hs[(colA+1)*HSTR + w0 + 4] = packbf(v3, p3);
            }
        }
    }
    __syncthreads();

    // ---- GEMM2: 8 warps, warp tile 16(M) x 64(N), K=256 ----
    int wm2 = warp * 16;
    int m16b = warp;
    float c2[8][4];
    #pragma unroll
    for (int nt = 0; nt < 8; nt++)
        #pragma unroll
        for (int q = 0; q < 4; q++) c2[nt][q] = 0.f;

    #pragma unroll
    for (int st = 0; st < 16; st++) {          // 16 k16 steps
        int kw = st * 8;
        unsigned a[4], bw[8][2];
        *(uint4*)a = g_w2f[(m16b*16 + st)*32 + lane];
        #pragma unroll
        for (int nt = 0; nt < 8; nt++) {
            int nc = nt*8 + lm;
            bw[nt][0] = Hs[nc*HSTR + kw + lk];
            bw[nt][1] = Hs[nc*HSTR + kw + 4 + lk];
        }
        #pragma unroll
        for (int nt = 0; nt < 8; nt++)
            MMA_BF16(c2[nt], a, bw[nt]);
    }

    // ---- epilogue: out = enhanced + ffn + b2 ----
    {
        int mr = wm2 + lm;
        float bi0 = b2[mr], bi1 = b2[mr + 8];
        #pragma unroll
        for (int nt = 0; nt < 8; nt++) {
            int col = nt*8 + 2*lk;
            size_t o0 = (size_t)(b*CC + mr) * PP + n0 + col;
            size_t o1 = o0 + (size_t)8 * PP;
            float2 e0 = *(const float2*)&g_enh[o0];
            float2 e1 = *(const float2*)&g_enh[o1];
            float2 v0, v1;
            v0.x = c2[nt][0] + bi0 + e0.x;
            v0.y = c2[nt][1] + bi0 + e0.y;
            v1.x = c2[nt][2] + bi1 + e1.x;
            v1.y = c2[nt][3] + bi1 + e1.y;
            *(float2*)&out[o0] = v0;
            *(float2*)&out[o1] = v1;
        }
    }
}

// ---------------- launch ----------------
extern "C" void kernel_launch(void* const* d_in, const int* in_sizes, int n_in,
                              void* d_out, int out_size) {
    const float* x   = (const float*)d_in[0];
    const float* gnw = (const float*)d_in[1];
    const float* gnb = (const float*)d_in[2];
    const float* w1  = (const float*)d_in[3];
    const float* b1  = (const float*)d_in[4];
    const float* w2  = (const float*)d_in[5];
    const float* b2  = (const float*)d_in[6];
    float* out = (float*)d_out;

    const int smem_ffn = (64*ESTR + 64*HSTR) * 4;      // 51200 B -> 2 CTAs/SM
    cudaFuncSetAttribute(k_ffn, cudaFuncAttributeMaxDynamicSharedMemorySize, smem_ffn);

    k_stats<<<NBLK + 32, 256>>>(x, w1, w2);            // +32 blocks: W->frag bf16
    k_df   <<<NBLK, 256>>>();
    k_gn   <<<1, 128>>>();
    k_main <<<dim3(WW/TW, HH/TH, BB), dim3(TW, TH, 2)>>>(x, gnw, gnb);
    k_ffn  <<<dim3(PP/NT, BB), 256, smem_ffn>>>(b1, b2, out);
}